// round 9
// baseline (speedup 1.0000x reference)
#include <cuda_runtime.h>
#include <cstdint>

typedef uint32_t u32;

#define Bb 8
#define Mm 2048
#define NNs 2048
#define Dd 128
#define BM 64
#define BN 64
#define TPB 384
#define NCT 256          /* compute threads (warps 0-7) */
#define NT 32

#define C2 0.7213475204444817f   /* 0.5 * log2(e) */
#define INV_KEEP 1.25f

// pre-split bf16 copies of x1/x2 (hi/lo), packed u32 pairs, linear layout
__device__ u32 gQH[Bb*Mm*Dd/2], gQL[Bb*Mm*Dd/2];
__device__ u32 gKH[Bb*NNs*Dd/2], gKL[Bb*NNs*Dd/2];

// ---- smem byte offsets (per CTA, total 115712 = fits 2 CTAs/SM) ----
#define OF_QH  0        /* 64x128 bf16 = 16KB */
#define OF_QL  16384
#define OF_K0  32768    /* KH 16KB + KL 16KB */
#define OF_K1  65536
#define OF_PH  98304    /* P hi: 64 x 64 bf16 = 8KB (128B rows) */
#define OF_PL  106496
#define OF_MK  114688   /* 2 x 512B keep-bit buffers; reused as RED in epilogue */
#define SMEM_TOTAL 115712

__device__ __forceinline__ u32 swa(u32 base, int row, int colb){
    return base + (u32)(row * 256) + (u32)((((colb >> 4) ^ (row & 7)) << 4) + (colb & 15));
}
__device__ __forceinline__ u32 swp(u32 base, int row, int colb){
    return base + (u32)(row * 128) + (u32)(((((colb >> 4) ^ (row & 7)) & 7) << 4) + (colb & 15));
}
__device__ __forceinline__ void ldsm4(u32* r, u32 a){
    asm volatile("ldmatrix.sync.aligned.m8n8.x4.shared.b16 {%0,%1,%2,%3},[%4];"
        : "=r"(r[0]),"=r"(r[1]),"=r"(r[2]),"=r"(r[3]) : "r"(a));
}
__device__ __forceinline__ void ldsm4t(u32* r, u32 a){
    asm volatile("ldmatrix.sync.aligned.m8n8.x4.trans.shared.b16 {%0,%1,%2,%3},[%4];"
        : "=r"(r[0]),"=r"(r[1]),"=r"(r[2]),"=r"(r[3]) : "r"(a));
}
__device__ __forceinline__ void mmabf(float* c, const u32* a, u32 b0, u32 b1){
    asm volatile("mma.sync.aligned.m16n8k16.row.col.f32.bf16.bf16.f32 "
        "{%0,%1,%2,%3},{%4,%5,%6,%7},{%8,%9},{%0,%1,%2,%3};"
        : "+f"(c[0]),"+f"(c[1]),"+f"(c[2]),"+f"(c[3])
        : "r"(a[0]),"r"(a[1]),"r"(a[2]),"r"(a[3]),"r"(b0),"r"(b1));
}
__device__ __forceinline__ void split_pair(float p0, float p1, u32& h2, u32& l2){
    asm("cvt.rn.bf16x2.f32 %0, %1, %2;" : "=r"(h2) : "f"(p1), "f"(p0));
    float h0 = __uint_as_float(h2 << 16);
    float h1 = __uint_as_float(h2 & 0xffff0000u);
    float r0 = p0 - h0, r1 = p1 - h1;
    asm("cvt.rn.bf16x2.f32 %0, %1, %2;" : "=r"(l2) : "f"(r1), "f"(r0));
}
__device__ __forceinline__ float ex2f(float x){
    float r; asm("ex2.approx.f32 %0, %1;" : "=f"(r) : "f"(x)); return r;
}

// JAX threefry2x32 partitionable, bit-exact (frozen since R1).
__device__ __forceinline__ u32 tf_keep(u32 ctr)
{
    const u32 K1 = 42u;
    const u32 K2 = 0x1BD11BDAu ^ 42u;
    u32 x0 = 0u;
    u32 x1 = ctr + K1;
#define TF_RND(r) { x0 += x1; x1 = __funnelshift_l(x1, x1, (r)); x1 ^= x0; }
    TF_RND(13) TF_RND(15) TF_RND(26) TF_RND(6)
    x0 += K1; x1 += K2 + 1u;
    TF_RND(17) TF_RND(29) TF_RND(16) TF_RND(24)
    x0 += K2; x1 += 0u + 2u;
    TF_RND(13) TF_RND(15) TF_RND(26) TF_RND(6)
    x0 += 0u; x1 += K1 + 3u;
    TF_RND(17) TF_RND(29) TF_RND(16) TF_RND(24)
    x0 += K1; x1 += K2 + 4u;
    TF_RND(13) TF_RND(15) TF_RND(26) TF_RND(6)
    x0 += K2; x1 += 0u + 5u;
#undef TF_RND
    return (((x0 ^ x1) >> 9) <= 6710886u) ? 1u : 0u;
}

__global__ void __launch_bounds__(256)
split_prepass(const float* __restrict__ x1, const float* __restrict__ x2)
{
    int i = blockIdx.x * 256 + threadIdx.x;
    int half = i >> 19;
    int j = i & 0x7FFFF;
    const float4* src = (const float4*)(half ? x2 : x1);
    float4 v = src[j];
    u32 h0,l0,h1,l1;
    split_pair(v.x, v.y, h0, l0);
    split_pair(v.z, v.w, h1, l1);
    uint2* dh = (uint2*)(half ? gKH : gQH);
    uint2* dl = (uint2*)(half ? gKL : gQL);
    dh[j] = make_uint2(h0, h1);
    dl[j] = make_uint2(l0, l1);
}

// cp.async one 64-row bf16 K tile pair (hi+lo); 256 threads, 8 chunks each
__device__ __forceinline__ void cp_k(u32 bufbase, int b, int n0, int tid){
    #pragma unroll
    for (int k = 0; k < 8; k++){
        int idx  = tid + k * NCT;           // 0..2047
        int half = idx >> 10;
        int ci   = idx & 1023;
        int row  = ci >> 4;
        int c    = ci & 15;
        u32 da = bufbase + (u32)(half * 16384) + (u32)(row * 256) + (u32)((c ^ (row & 7)) << 4);
        const char* s = (const char*)(half ? gKL : gKH)
                      + ((size_t)(b * NNs + n0 + row) * 256 + c * 16);
        asm volatile("cp.async.cg.shared.global [%0], [%1], 16;" :: "r"(da), "l"(s));
    }
}

__global__ void __launch_bounds__(TPB, 2)
attn_hmma(const float* __restrict__ x1, const float* __restrict__ x2, float* __restrict__ out)
{
    extern __shared__ char sm[];
    const u32 smb = (u32)__cvta_generic_to_shared(sm);
    const int tid  = threadIdx.x;
    const int w    = tid >> 5;
    const int lane = tid & 31;
    const int gID  = lane >> 2;
    const int tig  = lane & 3;
    const int g    = w >> 1;          // compute: rows 16g..16g+15 (g 0..3)
    const int s    = w & 1;           // compute: col half
    const int b    = blockIdx.y;
    const int mrow0 = blockIdx.x * BM;

    const u32 QH = smb + OF_QH, QL = smb + OF_QL;
    const u32 PH = smb + OF_PH, PL = smb + OF_PL;

    // ---- prologue ----
    if (tid < NCT){
        // Q hi+lo: 2048 16B chunks
        #pragma unroll
        for (int k = 0; k < 8; k++){
            int idx = tid + k * NCT;
            int half = idx >> 10;
            int ci = idx & 1023;
            int row = ci >> 4, c = ci & 15;
            u32 da = (half ? QL : QH) + (u32)(row * 256) + (u32)((c ^ (row & 7)) << 4);
            const char* src = (const char*)(half ? gQL : gQH)
                            + ((size_t)(b * Mm + mrow0 + row) * 256 + c * 16);
            asm volatile("cp.async.cg.shared.global [%0], [%1], 16;" :: "r"(da), "l"(src));
        }
        cp_k(smb + OF_K0, b, 0, tid);
        asm volatile("cp.async.commit_group;");
        asm volatile("cp.async.wait_group 0;" ::: "memory");
    } else {
        // mask warps (w 8..11): tile-0 keep bits -> buffer 0
        int idx = (w - 8) * 32 + lane;     // 0..127 word index
        int row = idx >> 1, half = idx & 1;
        u32 base = ((u32)(b * Mm + mrow0 + row)) * 2048u + (u32)(half * 32);
        u32 m0 = 0;
        #pragma unroll 4
        for (int j = 0; j < 32; j++)
            m0 |= tf_keep(base + (u32)j) << j;
        ((u32*)(sm + OF_MK))[idx] = m0;
    }

    const int rA  = ((lane >> 3) & 1) * 8 + (lane & 7);
    const int cA  = ((lane >> 4) & 1) * 16;
    const int rBq = ((lane >> 4) & 1) * 8 + (lane & 7);
    const int cBq = ((lane >> 3) & 1) * 16;

    float o[8][4];
    #pragma unroll
    for (int i = 0; i < 8; i++){ o[i][0]=o[i][1]=o[i][2]=o[i][3]=0.f; }
    float lsum0 = 0.f, lsum1 = 0.f;

    __syncthreads();

    for (int t = 0; t < NT; t++){
        const u32 KB = smb + ((t & 1) ? OF_K1 : OF_K0);
        const u32 KHt = KB, KLt = KB + 16384;

        if (tid < NCT && t < NT - 1){
            cp_k(smb + (((t + 1) & 1) ? OF_K1 : OF_K0), b, (t + 1) * BN, tid);
            asm volatile("cp.async.commit_group;");
        }

        if (w < 8){
            // ---- QK: S(16x32) = Qh*Kh + Qh*Kl + Ql*Kh ----
            float s4[4][4];
            #pragma unroll
            for (int i = 0; i < 4; i++){ s4[i][0]=s4[i][1]=s4[i][2]=s4[i][3]=0.f; }

            #pragma unroll
            for (int k = 0; k < 8; k++){
                int dby = k * 32;
                u32 ah[4], al[4];
                ldsm4(ah, swa(QH, 16 * g + rA, dby + cA));
                ldsm4(al, swa(QL, 16 * g + rA, dby + cA));
                #pragma unroll
                for (int nb = 0; nb < 2; nb++){
                    u32 bh[4], bl[4];
                    ldsm4(bh, swa(KHt, 32 * s + nb * 16 + rBq, dby + cBq));
                    ldsm4(bl, swa(KLt, 32 * s + nb * 16 + rBq, dby + cBq));
                    mmabf(s4[2*nb],   ah, bh[0], bh[1]);
                    mmabf(s4[2*nb],   ah, bl[0], bl[1]);
                    mmabf(s4[2*nb],   al, bh[0], bh[1]);
                    mmabf(s4[2*nb+1], ah, bh[2], bh[3]);
                    mmabf(s4[2*nb+1], ah, bl[2], bl[3]);
                    mmabf(s4[2*nb+1], al, bh[2], bh[3]);
                }
            }

            // ---- softmax + dropout (mask bits from smem) -> P hi/lo ----
            const u32* mk = (const u32*)(sm + OF_MK + ((t & 1) ? 512 : 0));
            int r0 = 16 * g + gID;
            u32 mw0 = mk[r0 * 2 + s];
            u32 mw1 = mk[(r0 + 8) * 2 + s];
            #pragma unroll
            for (int nb = 0; nb < 4; nb++){
                float* c = s4[nb];
                float p0 = ex2f(c[0] * C2);
                float p1 = ex2f(c[1] * C2);
                float p2 = ex2f(c[2] * C2);
                float p3 = ex2f(c[3] * C2);
                lsum0 += p0 + p1;
                lsum1 += p2 + p3;
                int bit = 8 * nb + 2 * tig;
                float q0 = ((mw0 >> bit) & 1u)       ? p0 * INV_KEEP : 0.f;
                float q1 = ((mw0 >> (bit + 1)) & 1u) ? p1 * INV_KEEP : 0.f;
                float q2 = ((mw1 >> bit) & 1u)       ? p2 * INV_KEEP : 0.f;
                float q3 = ((mw1 >> (bit + 1)) & 1u) ? p3 * INV_KEEP : 0.f;
                u32 h01, l01, h23, l23;
                split_pair(q0, q1, h01, l01);
                split_pair(q2, q3, h23, l23);
                int colb = 64 * s + 16 * nb + 4 * tig;
                *(u32*)(sm + swp(OF_PH, r0,     colb)) = h01;
                *(u32*)(sm + swp(OF_PH, r0 + 8, colb)) = h23;
                *(u32*)(sm + swp(OF_PL, r0,     colb)) = l01;
                *(u32*)(sm + swp(OF_PL, r0 + 8, colb)) = l23;
            }
            // pairwise barrier: only the two warps sharing row group g
            asm volatile("bar.sync %0, 64;" :: "r"(1 + g) : "memory");

            // ---- PV: O(16x64) += Ph*Vh + Ph*Vl + Pl*Vh ----
            #pragma unroll
            for (int kk = 0; kk < 4; kk++){
                u32 pA[4], pB[4];
                ldsm4(pA, swp(PH, 16 * g + rA, 32 * kk + cA));
                ldsm4(pB, swp(PL, 16 * g + rA, 32 * kk + cA));
                #pragma unroll
                for (int dgp = 0; dgp < 4; dgp++){
                    int colb = 128 * s + 32 * dgp + cA;
                    u32 bh[4], bl[4];
                    ldsm4t(bh, swa(KHt, 16 * kk + rA, colb));
                    ldsm4t(bl, swa(KLt, 16 * kk + rA, colb));
                    mmabf(o[2*dgp],   pA, bh[0], bh[1]);
                    mmabf(o[2*dgp],   pA, bl[0], bl[1]);
                    mmabf(o[2*dgp],   pB, bh[0], bh[1]);
                    mmabf(o[2*dgp+1], pA, bh[2], bh[3]);
                    mmabf(o[2*dgp+1], pA, bl[2], bl[3]);
                    mmabf(o[2*dgp+1], pB, bh[2], bh[3]);
                }
            }
        } else if (t < NT - 1){
            // ---- mask warps: keep bits for tile t+1 ----
            int idx = (w - 8) * 32 + lane;
            int row = idx >> 1, half = idx & 1;
            u32 base = ((u32)(b * Mm + mrow0 + row)) * 2048u
                     + (u32)((t + 1) * 64 + half * 32);
            u32 m0 = 0;
            #pragma unroll 4
            for (int j = 0; j < 32; j++)
                m0 |= tf_keep(base + (u32)j) << j;
            ((u32*)(sm + OF_MK + (((t + 1) & 1) ? 512 : 0)))[idx] = m0;
        }

        if (tid < NCT && t < NT - 1){
            asm volatile("cp.async.wait_group 0;" ::: "memory");
        }
        __syncthreads();   // K / P / mask buffers handed off
    }

    // ---- epilogue (RED overlays MK; masks are dead now) ----
    float* red = (float*)(sm + OF_MK);
    if (w < 8){
        lsum0 += __shfl_xor_sync(0xffffffffu, lsum0, 1);
        lsum0 += __shfl_xor_sync(0xffffffffu, lsum0, 2);
        lsum1 += __shfl_xor_sync(0xffffffffu, lsum1, 1);
        lsum1 += __shfl_xor_sync(0xffffffffu, lsum1, 2);
        if (tig == 0){
            red[(16 * g + gID) * 2 + s]     = lsum0;
            red[(16 * g + gID + 8) * 2 + s] = lsum1;
        }
    }
    __syncthreads();
    if (w < 8){
        int r0 = 16 * g + gID;
        float inv0 = 1.0f / (red[r0 * 2] + red[r0 * 2 + 1]);
        float inv1 = 1.0f / (red[(r0 + 8) * 2] + red[(r0 + 8) * 2 + 1]);

        float* g0 = out + ((size_t)b * Mm + mrow0 + r0) * Dd + 64 * s;
        float* g1 = g0 + 8 * Dd;
        #pragma unroll
        for (int db = 0; db < 8; db++){
            int d = db * 8 + 2 * tig;
            *(float2*)(g0 + d) = make_float2(o[db][0] * inv0, o[db][1] * inv0);
            *(float2*)(g1 + d) = make_float2(o[db][2] * inv1, o[db][3] * inv1);
        }
    }
}

extern "C" void kernel_launch(void* const* d_in, const int* in_sizes, int n_in,
                              void* d_out, int out_size)
{
    const float* x1 = (const float*)d_in[0];
    const float* x2 = (const float*)d_in[1];
    float* out = (float*)d_out;

    split_prepass<<<4096, 256>>>(x1, x2);

    cudaFuncSetAttribute(attn_hmma, cudaFuncAttributeMaxDynamicSharedMemorySize, SMEM_TOTAL);
    dim3 grid(Mm / BM, Bb);
    attn_hmma<<<grid, TPB, SMEM_TOTAL>>>(x1, x2, out);
}

// round 10
// speedup vs baseline: 1.0163x; 1.0163x over previous
#include <cuda_runtime.h>
#include <cstdint>

typedef uint32_t u32;

#define Bb 8
#define Mm 2048
#define NNs 2048
#define Dd 128
#define BM 128
#define BN 64
#define TPB 640
#define NCT 512          /* compute threads (warps 0-15) */
#define NT 32

#define C2 0.7213475204444817f   /* 0.5 * log2(e) */
#define INV_KEEP 1.25f

// pre-split bf16 copies of x1/x2 (hi/lo), packed u32 pairs, linear layout
__device__ u32 gQH[Bb*Mm*Dd/2], gQL[Bb*Mm*Dd/2];
__device__ u32 gKH[Bb*NNs*Dd/2], gKL[Bb*NNs*Dd/2];

// ---- smem byte offsets ----
#define OF_QH  0        /* 128x128 bf16 = 32KB */
#define OF_QL  32768
#define OF_K0  65536    /* KH 16KB + KL 16KB */
#define OF_K1  98304
#define OF_PH  131072   /* P hi: 128 x 64 bf16 = 16KB (128B rows) */
#define OF_PL  147456
#define OF_MK  163840   /* 2 x 1KB keep-bit buffers */
#define OF_RED 165888   /* 256 floats */
#define SMEM_TOTAL 166912

// named barrier ids: 1..8 pairwise P, 11 compute-all, 12/13 mask-full, 14/15 mask-empty
#define BAR_CMP 11

__device__ __forceinline__ void bar_sync(int id, int cnt){
    asm volatile("bar.sync %0, %1;" :: "r"(id), "r"(cnt) : "memory");
}
__device__ __forceinline__ void bar_arrive(int id, int cnt){
    asm volatile("bar.arrive %0, %1;" :: "r"(id), "r"(cnt) : "memory");
}

__device__ __forceinline__ u32 swa(u32 base, int row, int colb){
    return base + (u32)(row * 256) + (u32)((((colb >> 4) ^ (row & 7)) << 4) + (colb & 15));
}
__device__ __forceinline__ u32 swp(u32 base, int row, int colb){
    return base + (u32)(row * 128) + (u32)(((((colb >> 4) ^ (row & 7)) & 7) << 4) + (colb & 15));
}
__device__ __forceinline__ void ldsm4(u32* r, u32 a){
    asm volatile("ldmatrix.sync.aligned.m8n8.x4.shared.b16 {%0,%1,%2,%3},[%4];"
        : "=r"(r[0]),"=r"(r[1]),"=r"(r[2]),"=r"(r[3]) : "r"(a));
}
__device__ __forceinline__ void ldsm4t(u32* r, u32 a){
    asm volatile("ldmatrix.sync.aligned.m8n8.x4.trans.shared.b16 {%0,%1,%2,%3},[%4];"
        : "=r"(r[0]),"=r"(r[1]),"=r"(r[2]),"=r"(r[3]) : "r"(a));
}
__device__ __forceinline__ void mmabf(float* c, const u32* a, u32 b0, u32 b1){
    asm volatile("mma.sync.aligned.m16n8k16.row.col.f32.bf16.bf16.f32 "
        "{%0,%1,%2,%3},{%4,%5,%6,%7},{%8,%9},{%0,%1,%2,%3};"
        : "+f"(c[0]),"+f"(c[1]),"+f"(c[2]),"+f"(c[3])
        : "r"(a[0]),"r"(a[1]),"r"(a[2]),"r"(a[3]),"r"(b0),"r"(b1));
}
__device__ __forceinline__ void split_pair(float p0, float p1, u32& h2, u32& l2){
    asm("cvt.rn.bf16x2.f32 %0, %1, %2;" : "=r"(h2) : "f"(p1), "f"(p0));
    float h0 = __uint_as_float(h2 << 16);
    float h1 = __uint_as_float(h2 & 0xffff0000u);
    float r0 = p0 - h0, r1 = p1 - h1;
    asm("cvt.rn.bf16x2.f32 %0, %1, %2;" : "=r"(l2) : "f"(r1), "f"(r0));
}
__device__ __forceinline__ float ex2f(float x){
    float r; asm("ex2.approx.f32 %0, %1;" : "=f"(r) : "f"(x)); return r;
}

// JAX threefry2x32 partitionable, bit-exact (frozen since R1).
__device__ __forceinline__ u32 tf_keep(u32 ctr)
{
    const u32 K1 = 42u;
    const u32 K2 = 0x1BD11BDAu ^ 42u;
    u32 x0 = 0u;
    u32 x1 = ctr + K1;
#define TF_RND(r) { x0 += x1; x1 = __funnelshift_l(x1, x1, (r)); x1 ^= x0; }
    TF_RND(13) TF_RND(15) TF_RND(26) TF_RND(6)
    x0 += K1; x1 += K2 + 1u;
    TF_RND(17) TF_RND(29) TF_RND(16) TF_RND(24)
    x0 += K2; x1 += 0u + 2u;
    TF_RND(13) TF_RND(15) TF_RND(26) TF_RND(6)
    x0 += 0u; x1 += K1 + 3u;
    TF_RND(17) TF_RND(29) TF_RND(16) TF_RND(24)
    x0 += K1; x1 += K2 + 4u;
    TF_RND(13) TF_RND(15) TF_RND(26) TF_RND(6)
    x0 += K2; x1 += 0u + 5u;
#undef TF_RND
    return (((x0 ^ x1) >> 9) <= 6710886u) ? 1u : 0u;
}

__global__ void __launch_bounds__(256)
split_prepass(const float* __restrict__ x1, const float* __restrict__ x2)
{
    int i = blockIdx.x * 256 + threadIdx.x;
    int half = i >> 19;
    int j = i & 0x7FFFF;
    const float4* src = (const float4*)(half ? x2 : x1);
    float4 v = src[j];
    u32 h0,l0,h1,l1;
    split_pair(v.x, v.y, h0, l0);
    split_pair(v.z, v.w, h1, l1);
    uint2* dh = (uint2*)(half ? gKH : gQH);
    uint2* dl = (uint2*)(half ? gKL : gQL);
    dh[j] = make_uint2(h0, h1);
    dl[j] = make_uint2(l0, l1);
}

// cp.async one 64-row bf16 K tile pair (hi+lo); 512 threads, 4 chunks each
__device__ __forceinline__ void cp_k(u32 bufbase, int b, int n0, int tid){
    #pragma unroll
    for (int k = 0; k < 4; k++){
        int idx  = tid + k * NCT;           // 0..2047
        int half = idx >> 10;
        int ci   = idx & 1023;
        int row  = ci >> 4;
        int c    = ci & 15;
        u32 da = bufbase + (u32)(half * 16384) + (u32)(row * 256) + (u32)((c ^ (row & 7)) << 4);
        const char* s = (const char*)(half ? gKL : gKH)
                      + ((size_t)(b * NNs + n0 + row) * 256 + c * 16);
        asm volatile("cp.async.cg.shared.global [%0], [%1], 16;" :: "r"(da), "l"(s));
    }
}

__global__ void __launch_bounds__(TPB, 1)
attn_hmma(const float* __restrict__ x1, const float* __restrict__ x2, float* __restrict__ out)
{
    extern __shared__ char sm[];
    const u32 smb = (u32)__cvta_generic_to_shared(sm);
    const int tid  = threadIdx.x;
    const int w    = tid >> 5;
    const int lane = tid & 31;
    const int gID  = lane >> 2;
    const int tig  = lane & 3;
    const int b    = blockIdx.y;
    const int mrow0 = blockIdx.x * BM;

    if (w >= 16){
        // ================= MASK WARPS: free-running threefry producer ======
        int idx = (w - 16) * 32 + lane;     // 0..127 -> row
        u32 base0 = ((u32)(b * Mm + mrow0 + idx)) * 2048u;
        u32* mk0 = (u32*)(sm + OF_MK);
        u32* mk1 = (u32*)(sm + OF_MK + 1024);
        for (int t = 0; t < NT; t++){
            if (t >= 2) bar_sync(14 + (t & 1), TPB);   // wait buffer consumed
            u32 base = base0 + (u32)(t * 64);
            u32 m0 = 0, m1 = 0;
            #pragma unroll 4
            for (int j = 0; j < 32; j++){
                m0 |= tf_keep(base + (u32)j) << j;
                m1 |= tf_keep(base + 32u + (u32)j) << j;
            }
            u32* mk = (t & 1) ? mk1 : mk0;
            mk[idx * 2]     = m0;
            mk[idx * 2 + 1] = m1;
            bar_arrive(12 + (t & 1), TPB);             // publish tile t
        }
        return;
    }

    // ================= COMPUTE WARPS =======================================
    const int g = w >> 1;             // row group 0..7: rows 16g..16g+15
    const int s = w & 1;              // col half
    const u32 QH = smb + OF_QH, QL = smb + OF_QL;
    const u32 PH = smb + OF_PH, PL = smb + OF_PL;

    // prologue: Q hi+lo + K tile 0
    #pragma unroll
    for (int k = 0; k < 8; k++){
        int idx = tid + k * NCT;        // 0..4095
        int half = idx >> 11;
        int ci = idx & 2047;
        int row = ci >> 4, c = ci & 15;
        u32 da = (half ? QL : QH) + (u32)(row * 256) + (u32)((c ^ (row & 7)) << 4);
        const char* src = (const char*)(half ? gQL : gQH)
                        + ((size_t)(b * Mm + mrow0 + row) * 256 + c * 16);
        asm volatile("cp.async.cg.shared.global [%0], [%1], 16;" :: "r"(da), "l"(src));
    }
    cp_k(smb + OF_K0, b, 0, tid);
    asm volatile("cp.async.commit_group;");

    const int rA  = ((lane >> 3) & 1) * 8 + (lane & 7);
    const int cA  = ((lane >> 4) & 1) * 16;
    const int rBq = ((lane >> 4) & 1) * 8 + (lane & 7);
    const int cBq = ((lane >> 3) & 1) * 16;

    float o[8][4];
    #pragma unroll
    for (int i = 0; i < 8; i++){ o[i][0]=o[i][1]=o[i][2]=o[i][3]=0.f; }
    float lsum0 = 0.f, lsum1 = 0.f;

    asm volatile("cp.async.wait_group 0;" ::: "memory");
    bar_sync(BAR_CMP, NCT);

    for (int t = 0; t < NT; t++){
        const u32 KB = smb + ((t & 1) ? OF_K1 : OF_K0);
        const u32 KHt = KB, KLt = KB + 16384;

        if (t < NT - 1){
            cp_k(smb + (((t + 1) & 1) ? OF_K1 : OF_K0), b, (t + 1) * BN, tid);
            asm volatile("cp.async.commit_group;");
        }

        // ---- QK: S(16x32) = Qh*Kh + Qh*Kl + Ql*Kh ----
        float s4[4][4];
        #pragma unroll
        for (int i = 0; i < 4; i++){ s4[i][0]=s4[i][1]=s4[i][2]=s4[i][3]=0.f; }

        #pragma unroll
        for (int k = 0; k < 8; k++){
            int dby = k * 32;
            u32 ah[4], al[4];
            ldsm4(ah, swa(QH, 16 * g + rA, dby + cA));
            ldsm4(al, swa(QL, 16 * g + rA, dby + cA));
            #pragma unroll
            for (int nb = 0; nb < 2; nb++){
                u32 bh[4], bl[4];
                ldsm4(bh, swa(KHt, 32 * s + nb * 16 + rBq, dby + cBq));
                ldsm4(bl, swa(KLt, 32 * s + nb * 16 + rBq, dby + cBq));
                mmabf(s4[2*nb],   ah, bh[0], bh[1]);
                mmabf(s4[2*nb],   ah, bl[0], bl[1]);
                mmabf(s4[2*nb],   al, bh[0], bh[1]);
                mmabf(s4[2*nb+1], ah, bh[2], bh[3]);
                mmabf(s4[2*nb+1], ah, bl[2], bl[3]);
                mmabf(s4[2*nb+1], al, bh[2], bh[3]);
            }
        }

        // ---- consume mask tile t ----
        bar_sync(12 + (t & 1), TPB);               // mask[t] published
        const u32* mk = (const u32*)(sm + OF_MK + ((t & 1) ? 1024 : 0));
        int r0 = 16 * g + gID;
        u32 mw0 = mk[r0 * 2 + s];
        u32 mw1 = mk[(r0 + 8) * 2 + s];
        bar_arrive(14 + (t & 1), TPB);             // buffer free for t+2

        // ---- softmax + dropout -> P hi/lo ----
        #pragma unroll
        for (int nb = 0; nb < 4; nb++){
            float* c = s4[nb];
            float p0 = ex2f(c[0] * C2);
            float p1 = ex2f(c[1] * C2);
            float p2 = ex2f(c[2] * C2);
            float p3 = ex2f(c[3] * C2);
            lsum0 += p0 + p1;
            lsum1 += p2 + p3;
            int bit = 8 * nb + 2 * tig;
            float q0 = ((mw0 >> bit) & 1u)       ? p0 * INV_KEEP : 0.f;
            float q1 = ((mw0 >> (bit + 1)) & 1u) ? p1 * INV_KEEP : 0.f;
            float q2 = ((mw1 >> bit) & 1u)       ? p2 * INV_KEEP : 0.f;
            float q3 = ((mw1 >> (bit + 1)) & 1u) ? p3 * INV_KEEP : 0.f;
            u32 h01, l01, h23, l23;
            split_pair(q0, q1, h01, l01);
            split_pair(q2, q3, h23, l23);
            int colb = 64 * s + 16 * nb + 4 * tig;
            *(u32*)(sm + swp(OF_PH, r0,     colb)) = h01;
            *(u32*)(sm + swp(OF_PH, r0 + 8, colb)) = h23;
            *(u32*)(sm + swp(OF_PL, r0,     colb)) = l01;
            *(u32*)(sm + swp(OF_PL, r0 + 8, colb)) = l23;
        }
        bar_sync(1 + g, 64);                       // P visible within row pair

        // ---- PV: O(16x64) += Ph*Vh + Ph*Vl + Pl*Vh ----
        #pragma unroll
        for (int kk = 0; kk < 4; kk++){
            u32 pA[4], pB[4];
            ldsm4(pA, swp(PH, 16 * g + rA, 32 * kk + cA));
            ldsm4(pB, swp(PL, 16 * g + rA, 32 * kk + cA));
            #pragma unroll
            for (int dgp = 0; dgp < 4; dgp++){
                int colb = 128 * s + 32 * dgp + cA;
                u32 bh[4], bl[4];
                ldsm4t(bh, swa(KHt, 16 * kk + rA, colb));
                ldsm4t(bl, swa(KLt, 16 * kk + rA, colb));
                mmabf(o[2*dgp],   pA, bh[0], bh[1]);
                mmabf(o[2*dgp],   pA, bl[0], bl[1]);
                mmabf(o[2*dgp],   pB, bh[0], bh[1]);
                mmabf(o[2*dgp+1], pA, bh[2], bh[3]);
                mmabf(o[2*dgp+1], pA, bl[2], bl[3]);
                mmabf(o[2*dgp+1], pB, bh[2], bh[3]);
            }
        }

        if (t < NT - 1){
            asm volatile("cp.async.wait_group 0;" ::: "memory");
        }
        bar_sync(BAR_CMP, NCT);    // K & P handoff (compute warps only)
    }

    // ---- epilogue ----
    float* red = (float*)(sm + OF_RED);
    lsum0 += __shfl_xor_sync(0xffffffffu, lsum0, 1);
    lsum0 += __shfl_xor_sync(0xffffffffu, lsum0, 2);
    lsum1 += __shfl_xor_sync(0xffffffffu, lsum1, 1);
    lsum1 += __shfl_xor_sync(0xffffffffu, lsum1, 2);
    if (tig == 0){
        red[(16 * g + gID) * 2 + s]     = lsum0;
        red[(16 * g + gID + 8) * 2 + s] = lsum1;
    }
    bar_sync(BAR_CMP, NCT);
    {
        int r0 = 16 * g + gID;
        float inv0 = 1.0f / (red[r0 * 2] + red[r0 * 2 + 1]);
        float inv1 = 1.0f / (red[(r0 + 8) * 2] + red[(r0 + 8) * 2 + 1]);

        float* g0 = out + ((size_t)b * Mm + mrow0 + r0) * Dd + 64 * s;
        float* g1 = g0 + 8 * Dd;
        #pragma unroll
        for (int db = 0; db < 8; db++){
            int d = db * 8 + 2 * tig;
            *(float2*)(g0 + d) = make_float2(o[db][0] * inv0, o[db][1] * inv0);
            *(float2*)(g1 + d) = make_float2(o[db][2] * inv1, o[db][3] * inv1);
        }
    }
}

extern "C" void kernel_launch(void* const* d_in, const int* in_sizes, int n_in,
                              void* d_out, int out_size)
{
    const float* x1 = (const float*)d_in[0];
    const float* x2 = (const float*)d_in[1];
    float* out = (float*)d_out;

    split_prepass<<<4096, 256>>>(x1, x2);

    cudaFuncSetAttribute(attn_hmma, cudaFuncAttributeMaxDynamicSharedMemorySize, SMEM_TOTAL);
    dim3 grid(Mm / BM, Bb);
    attn_hmma<<<grid, TPB, SMEM_TOTAL>>>(x1, x2, out);
}

// round 11
// speedup vs baseline: 1.0307x; 1.0142x over previous
#include <cuda_runtime.h>
#include <cstdint>

typedef uint32_t u32;

#define Bb 8
#define Mm 2048
#define NNs 2048
#define Dd 128
#define BM 128
#define BN 64
#define TPB 640
#define NCT 512          /* compute threads (warps 0-15) */
#define NT 32

#define C2 0.7213475204444817f   /* 0.5 * log2(e) */
#define INV_KEEP 1.25f

// pre-split bf16 copies of x1/x2 (hi/lo), packed u32 pairs, linear layout
__device__ u32 gQH[Bb*Mm*Dd/2], gQL[Bb*Mm*Dd/2];
__device__ u32 gKH[Bb*NNs*Dd/2], gKL[Bb*NNs*Dd/2];

// ---- smem byte offsets ----
#define OF_QH   0        /* 128x128 bf16 = 32KB */
#define OF_QL   32768
#define OF_K0   65536    /* 3 x (KH 16KB + KL 16KB) ring */
#define OF_P0   163840   /* 2 x (PH 16KB + PL 16KB) ring */
#define OF_MK   229376   /* 2 x 1KB keep-bit buffers; RED overlay in epilogue */
#define OF_BAR  231424   /* mbarriers: KF0-2, KE0-2, MF0-1, ME0-1 (10 x 8B) */
#define SMEM_TOTAL 231680

#define BKF(i) (smb + OF_BAR + (u32)(i)*8u)
#define BKE(i) (smb + OF_BAR + 24u + (u32)(i)*8u)
#define BMF(i) (smb + OF_BAR + 48u + (u32)(i)*8u)
#define BME(i) (smb + OF_BAR + 64u + (u32)(i)*8u)

__device__ __forceinline__ void mwait(u32 addr, u32 ph){
    u32 done;
    asm volatile("{\n\t.reg .pred p;\n\t"
        "mbarrier.try_wait.parity.acquire.cta.shared::cta.b64 p, [%1], %2;\n\t"
        "selp.b32 %0, 1, 0, p;\n\t}"
        : "=r"(done) : "r"(addr), "r"(ph) : "memory");
    if (!done){
        asm volatile("{\n\t.reg .pred P1;\n\t"
            "WL_%=:\n\t"
            "mbarrier.try_wait.parity.acquire.cta.shared::cta.b64 P1, [%0], %1, 0x989680;\n\t"
            "@P1 bra.uni WD_%=;\n\t"
            "bra.uni WL_%=;\n\t"
            "WD_%=:\n\t}"
            :: "r"(addr), "r"(ph) : "memory");
    }
}
__device__ __forceinline__ void marr(u32 addr){
    asm volatile("mbarrier.arrive.shared.b64 _, [%0];" :: "r"(addr) : "memory");
}
__device__ __forceinline__ void mcparr(u32 addr){
    asm volatile("cp.async.mbarrier.arrive.noinc.shared::cta.b64 [%0];" :: "r"(addr) : "memory");
}
__device__ __forceinline__ void bar_pair(int id){
    asm volatile("bar.sync %0, 64;" :: "r"(id) : "memory");
}

__device__ __forceinline__ u32 swa(u32 base, int row, int colb){
    return base + (u32)(row * 256) + (u32)((((colb >> 4) ^ (row & 7)) << 4) + (colb & 15));
}
__device__ __forceinline__ u32 swp(u32 base, int row, int colb){
    return base + (u32)(row * 128) + (u32)(((((colb >> 4) ^ (row & 7)) & 7) << 4) + (colb & 15));
}
__device__ __forceinline__ void ldsm4(u32* r, u32 a){
    asm volatile("ldmatrix.sync.aligned.m8n8.x4.shared.b16 {%0,%1,%2,%3},[%4];"
        : "=r"(r[0]),"=r"(r[1]),"=r"(r[2]),"=r"(r[3]) : "r"(a));
}
__device__ __forceinline__ void ldsm4t(u32* r, u32 a){
    asm volatile("ldmatrix.sync.aligned.m8n8.x4.trans.shared.b16 {%0,%1,%2,%3},[%4];"
        : "=r"(r[0]),"=r"(r[1]),"=r"(r[2]),"=r"(r[3]) : "r"(a));
}
__device__ __forceinline__ void mmabf(float* c, const u32* a, u32 b0, u32 b1){
    asm volatile("mma.sync.aligned.m16n8k16.row.col.f32.bf16.bf16.f32 "
        "{%0,%1,%2,%3},{%4,%5,%6,%7},{%8,%9},{%0,%1,%2,%3};"
        : "+f"(c[0]),"+f"(c[1]),"+f"(c[2]),"+f"(c[3])
        : "r"(a[0]),"r"(a[1]),"r"(a[2]),"r"(a[3]),"r"(b0),"r"(b1));
}
__device__ __forceinline__ void split_pair(float p0, float p1, u32& h2, u32& l2){
    asm("cvt.rn.bf16x2.f32 %0, %1, %2;" : "=r"(h2) : "f"(p1), "f"(p0));
    float h0 = __uint_as_float(h2 << 16);
    float h1 = __uint_as_float(h2 & 0xffff0000u);
    float r0 = p0 - h0, r1 = p1 - h1;
    asm("cvt.rn.bf16x2.f32 %0, %1, %2;" : "=r"(l2) : "f"(r1), "f"(r0));
}
__device__ __forceinline__ float ex2f(float x){
    float r; asm("ex2.approx.f32 %0, %1;" : "=f"(r) : "f"(x)); return r;
}

// JAX threefry2x32 partitionable, bit-exact (frozen since R1).
__device__ __forceinline__ u32 tf_keep(u32 ctr)
{
    const u32 K1 = 42u;
    const u32 K2 = 0x1BD11BDAu ^ 42u;
    u32 x0 = 0u;
    u32 x1 = ctr + K1;
#define TF_RND(r) { x0 += x1; x1 = __funnelshift_l(x1, x1, (r)); x1 ^= x0; }
    TF_RND(13) TF_RND(15) TF_RND(26) TF_RND(6)
    x0 += K1; x1 += K2 + 1u;
    TF_RND(17) TF_RND(29) TF_RND(16) TF_RND(24)
    x0 += K2; x1 += 0u + 2u;
    TF_RND(13) TF_RND(15) TF_RND(26) TF_RND(6)
    x0 += 0u; x1 += K1 + 3u;
    TF_RND(17) TF_RND(29) TF_RND(16) TF_RND(24)
    x0 += K1; x1 += K2 + 4u;
    TF_RND(13) TF_RND(15) TF_RND(26) TF_RND(6)
    x0 += K2; x1 += 0u + 5u;
#undef TF_RND
    return (((x0 ^ x1) >> 9) <= 6710886u) ? 1u : 0u;
}

__global__ void __launch_bounds__(256)
split_prepass(const float* __restrict__ x1, const float* __restrict__ x2)
{
    int i = blockIdx.x * 256 + threadIdx.x;
    int half = i >> 19;
    int j = i & 0x7FFFF;
    const float4* src = (const float4*)(half ? x2 : x1);
    float4 v = src[j];
    u32 h0,l0,h1,l1;
    split_pair(v.x, v.y, h0, l0);
    split_pair(v.z, v.w, h1, l1);
    uint2* dh = (uint2*)(half ? gKH : gQH);
    uint2* dl = (uint2*)(half ? gKL : gQL);
    dh[j] = make_uint2(h0, h1);
    dl[j] = make_uint2(l0, l1);
}

// cp.async one 64-row bf16 K tile pair (hi+lo); 512 threads, 4 chunks each
__device__ __forceinline__ void cp_k(u32 bufbase, int b, int n0, int tid){
    #pragma unroll
    for (int k = 0; k < 4; k++){
        int idx  = tid + k * NCT;
        int half = idx >> 10;
        int ci   = idx & 1023;
        int row  = ci >> 4;
        int c    = ci & 15;
        u32 da = bufbase + (u32)(half * 16384) + (u32)(row * 256) + (u32)((c ^ (row & 7)) << 4);
        const char* s = (const char*)(half ? gKL : gKH)
                      + ((size_t)(b * NNs + n0 + row) * 256 + c * 16);
        asm volatile("cp.async.cg.shared.global [%0], [%1], 16;" :: "r"(da), "l"(s));
    }
}

// PV step: O += Ph*Vh + Ph*Vl + Pl*Vh
__device__ __forceinline__ void pv_step(float o[8][4], u32 PHb, u32 PLb, u32 KHb, u32 KLb,
                                        int g, int s, int rA, int cA){
    #pragma unroll
    for (int kk = 0; kk < 4; kk++){
        u32 pA[4], pB[4];
        ldsm4(pA, swp(PHb, 16 * g + rA, 32 * kk + cA));
        ldsm4(pB, swp(PLb, 16 * g + rA, 32 * kk + cA));
        #pragma unroll
        for (int dgp = 0; dgp < 4; dgp++){
            int colb = 128 * s + 32 * dgp + cA;
            u32 bh[4], bl[4];
            ldsm4t(bh, swa(KHb, 16 * kk + rA, colb));
            ldsm4t(bl, swa(KLb, 16 * kk + rA, colb));
            mmabf(o[2*dgp],   pA, bh[0], bh[1]);
            mmabf(o[2*dgp],   pA, bl[0], bl[1]);
            mmabf(o[2*dgp],   pB, bh[0], bh[1]);
            mmabf(o[2*dgp+1], pA, bh[2], bh[3]);
            mmabf(o[2*dgp+1], pA, bl[2], bl[3]);
            mmabf(o[2*dgp+1], pB, bh[2], bh[3]);
        }
    }
}

__global__ void __launch_bounds__(TPB, 1)
attn_hmma(const float* __restrict__ x1, const float* __restrict__ x2, float* __restrict__ out)
{
    extern __shared__ char sm[];
    const u32 smb = (u32)__cvta_generic_to_shared(sm);
    const int tid  = threadIdx.x;
    const int w    = tid >> 5;
    const int lane = tid & 31;
    const int gID  = lane >> 2;
    const int tig  = lane & 3;
    const int b    = blockIdx.y;
    const int mrow0 = blockIdx.x * BM;

    // ---- mbarrier init (before ANY arrive) ----
    if (tid == 0){
        #pragma unroll
        for (int i = 0; i < 3; i++){
            asm volatile("mbarrier.init.shared.b64 [%0], %1;" :: "r"(BKF(i)), "r"(NCT) : "memory");
            asm volatile("mbarrier.init.shared.b64 [%0], %1;" :: "r"(BKE(i)), "r"(NCT) : "memory");
        }
        #pragma unroll
        for (int i = 0; i < 2; i++){
            asm volatile("mbarrier.init.shared.b64 [%0], %1;" :: "r"(BMF(i)), "r"(128) : "memory");
            asm volatile("mbarrier.init.shared.b64 [%0], %1;" :: "r"(BME(i)), "r"(NCT) : "memory");
        }
    }
    __syncthreads();

    if (w >= 16){
        // ================= MASK WARPS: free-running threefry producer ======
        int idx = (w - 16) * 32 + lane;     // 0..127 -> row
        u32 base0 = ((u32)(b * Mm + mrow0 + idx)) * 2048u;
        #pragma unroll 1
        for (int t = 0; t < NT; t++){
            if (t >= 2) mwait(BME(t & 1), (u32)(((t >> 1) - 1) & 1));
            u32 base = base0 + (u32)(t * 64);
            u32 m0 = 0, m1 = 0;
            #pragma unroll 4
            for (int j = 0; j < 32; j++){
                m0 |= tf_keep(base + (u32)j) << j;
                m1 |= tf_keep(base + 32u + (u32)j) << j;
            }
            u32* mk = (u32*)(sm + OF_MK + ((t & 1) ? 1024 : 0));
            mk[idx * 2]     = m0;
            mk[idx * 2 + 1] = m1;
            marr(BMF(t & 1));
        }
        return;
    }

    // ================= COMPUTE WARPS =======================================
    const int g = w >> 1;             // row group 0..7
    const int s = w & 1;              // col half
    const u32 QH = smb + OF_QH, QL = smb + OF_QL;

    // prologue: Q hi+lo + K tile 0; single arrive covers both
    #pragma unroll
    for (int k = 0; k < 8; k++){
        int idx = tid + k * NCT;        // 0..4095
        int half = idx >> 11;
        int ci = idx & 2047;
        int row = ci >> 4, c = ci & 15;
        u32 da = (half ? QL : QH) + (u32)(row * 256) + (u32)((c ^ (row & 7)) << 4);
        const char* src = (const char*)(half ? gQL : gQH)
                        + ((size_t)(b * Mm + mrow0 + row) * 256 + c * 16);
        asm volatile("cp.async.cg.shared.global [%0], [%1], 16;" :: "r"(da), "l"(src));
    }
    cp_k(smb + OF_K0, b, 0, tid);
    mcparr(BKF(0));

    const int rA  = ((lane >> 3) & 1) * 8 + (lane & 7);
    const int cA  = ((lane >> 4) & 1) * 16;
    const int rBq = ((lane >> 4) & 1) * 8 + (lane & 7);
    const int cBq = ((lane >> 3) & 1) * 16;

    float o[8][4];
    #pragma unroll
    for (int i = 0; i < 8; i++){ o[i][0]=o[i][1]=o[i][2]=o[i][3]=0.f; }
    float lsum0 = 0.f, lsum1 = 0.f;

    #pragma unroll 1
    for (int t = 0; t < NT; t++){
        const int kb = t % 3;
        const u32 KB = smb + OF_K0 + (u32)(kb * 32768);
        const u32 KHt = KB, KLt = KB + 16384;

        // ---- K(t) ready ----
        mwait(BKF(kb), (u32)((t / 3) & 1));

        // ---- QK: S(16x32) = Qh*Kh + Qh*Kl + Ql*Kh ----
        float s4[4][4];
        #pragma unroll
        for (int i = 0; i < 4; i++){ s4[i][0]=s4[i][1]=s4[i][2]=s4[i][3]=0.f; }

        #pragma unroll
        for (int k = 0; k < 8; k++){
            int dby = k * 32;
            u32 ah[4], al[4];
            ldsm4(ah, swa(QH, 16 * g + rA, dby + cA));
            ldsm4(al, swa(QL, 16 * g + rA, dby + cA));
            #pragma unroll
            for (int nb = 0; nb < 2; nb++){
                u32 bh[4], bl[4];
                ldsm4(bh, swa(KHt, 32 * s + nb * 16 + rBq, dby + cBq));
                ldsm4(bl, swa(KLt, 32 * s + nb * 16 + rBq, dby + cBq));
                mmabf(s4[2*nb],   ah, bh[0], bh[1]);
                mmabf(s4[2*nb],   ah, bl[0], bl[1]);
                mmabf(s4[2*nb],   al, bh[0], bh[1]);
                mmabf(s4[2*nb+1], ah, bh[2], bh[3]);
                mmabf(s4[2*nb+1], ah, bl[2], bl[3]);
                mmabf(s4[2*nb+1], al, bh[2], bh[3]);
            }
        }

        // ---- PV(t-1): fills QK-chain latency with tensor work ----
        if (t > 0){
            const int kbp = (t - 1) % 3;
            const u32 KBp = smb + OF_K0 + (u32)(kbp * 32768);
            const u32 PHp = smb + OF_P0 + (u32)(((t - 1) & 1) * 32768);
            pv_step(o, PHp, PHp + 16384, KBp, KBp + 16384, g, s, rA, cA);
            marr(BKE(kbp));                    // K(t-1) consumed by this thread
        }

        // ---- prefetch K(t+1) (buffer (t+1)%3 == K(t-2)'s, freed in tile t-1) ----
        if (t < NT - 1){
            if (t >= 2) mwait(BKE((t + 1) % 3), (u32)(((t + 1) / 3 - 1) & 1));
            cp_k(smb + OF_K0 + (u32)(((t + 1) % 3) * 32768), b, (t + 1) * BN, tid);
            mcparr(BKF((t + 1) % 3));
        }

        // ---- mask tile t ----
        mwait(BMF(t & 1), (u32)((t >> 1) & 1));
        const u32* mk = (const u32*)(sm + OF_MK + ((t & 1) ? 1024 : 0));
        int r0 = 16 * g + gID;
        u32 mw0 = mk[r0 * 2 + s];
        u32 mw1 = mk[(r0 + 8) * 2 + s];
        marr(BME(t & 1));

        // ---- softmax + dropout -> P[t&1] hi/lo ----
        const u32 PHc = smb + OF_P0 + (u32)((t & 1) * 32768);
        const u32 PLc = PHc + 16384;
        #pragma unroll
        for (int nb = 0; nb < 4; nb++){
            float* c = s4[nb];
            float p0 = ex2f(c[0] * C2);
            float p1 = ex2f(c[1] * C2);
            float p2 = ex2f(c[2] * C2);
            float p3 = ex2f(c[3] * C2);
            lsum0 += p0 + p1;
            lsum1 += p2 + p3;
            int bit = 8 * nb + 2 * tig;
            float q0 = ((mw0 >> bit) & 1u)       ? p0 * INV_KEEP : 0.f;
            float q1 = ((mw0 >> (bit + 1)) & 1u) ? p1 * INV_KEEP : 0.f;
            float q2 = ((mw1 >> bit) & 1u)       ? p2 * INV_KEEP : 0.f;
            float q3 = ((mw1 >> (bit + 1)) & 1u) ? p3 * INV_KEEP : 0.f;
            u32 h01, l01, h23, l23;
            split_pair(q0, q1, h01, l01);
            split_pair(q2, q3, h23, l23);
            int colb = 64 * s + 16 * nb + 4 * tig;
            *(u32*)(sm + (swp(PHc, r0,     colb) - smb)) = h01;
            *(u32*)(sm + (swp(PHc, r0 + 8, colb) - smb)) = h23;
            *(u32*)(sm + (swp(PLc, r0,     colb) - smb)) = l01;
            *(u32*)(sm + (swp(PLc, r0 + 8, colb) - smb)) = l23;
        }
        bar_pair(1 + g);                       // P(t) visible within row pair
    }

    // ---- tail: PV(NT-1) ----
    {
        const int kbp = (NT - 1) % 3;
        const u32 KBp = smb + OF_K0 + (u32)(kbp * 32768);
        const u32 PHp = smb + OF_P0 + (u32)(((NT - 1) & 1) * 32768);
        pv_step(o, PHp, PHp + 16384, KBp, KBp + 16384, g, s, rA, cA);
    }

    // ---- epilogue (RED overlays mask data region) ----
    float* red = (float*)(sm + OF_MK);
    lsum0 += __shfl_xor_sync(0xffffffffu, lsum0, 1);
    lsum0 += __shfl_xor_sync(0xffffffffu, lsum0, 2);
    lsum1 += __shfl_xor_sync(0xffffffffu, lsum1, 1);
    lsum1 += __shfl_xor_sync(0xffffffffu, lsum1, 2);
    int r0 = 16 * g + gID;
    if (tig == 0){
        red[r0 * 2 + s]       = lsum0;
        red[(r0 + 8) * 2 + s] = lsum1;
    }
    bar_pair(1 + g);
    {
        float inv0 = 1.0f / (red[r0 * 2] + red[r0 * 2 + 1]);
        float inv1 = 1.0f / (red[(r0 + 8) * 2] + red[(r0 + 8) * 2 + 1]);

        float* g0 = out + ((size_t)b * Mm + mrow0 + r0) * Dd + 64 * s;
        float* g1 = g0 + 8 * Dd;
        #pragma unroll
        for (int db = 0; db < 8; db++){
            int d = db * 8 + 2 * tig;
            *(float2*)(g0 + d) = make_float2(o[db][0] * inv0, o[db][1] * inv0);
            *(float2*)(g1 + d) = make_float2(o[db][2] * inv1, o[db][3] * inv1);
        }
    }
}

extern "C" void kernel_launch(void* const* d_in, const int* in_sizes, int n_in,
                              void* d_out, int out_size)
{
    const float* x1 = (const float*)d_in[0];
    const float* x2 = (const float*)d_in[1];
    float* out = (float*)d_out;

    split_prepass<<<4096, 256>>>(x1, x2);

    cudaFuncSetAttribute(attn_hmma, cudaFuncAttributeMaxDynamicSharedMemorySize, SMEM_TOTAL);
    dim3 grid(Mm / BM, Bb);
    attn_hmma<<<grid, TPB, SMEM_TOTAL>>>(x1, x2, out);
}

// round 13
// speedup vs baseline: 1.1675x; 1.1326x over previous
#include <cuda_runtime.h>
#include <cuda_fp16.h>
#include <cstdint>

typedef uint32_t u32;

#define Bb 8
#define Mm 2048
#define NNs 2048
#define Dd 128
#define BM 128
#define BN 64
#define TPB 640
#define NCT 512          /* compute threads (warps 0-15) */
#define NT 32

#define C2 0.7213475204444817f   /* 0.5 * log2(e) */
#define INV_KEEP 1.25f

// pre-split fp16 copies of x1/x2 (hi/lo), packed u32 pairs, linear layout
__device__ u32 gQH[Bb*Mm*Dd/2], gQL[Bb*Mm*Dd/2];
__device__ u32 gKH[Bb*NNs*Dd/2], gKL[Bb*NNs*Dd/2];

// ---- smem byte offsets ----
#define OF_QH   0        /* 128x128 fp16 = 32KB */
#define OF_QL   32768
#define OF_K0   65536    /* 3 x (KH 16KB + KL 16KB) ring */
#define OF_P0   163840   /* 2 x PH(fp16) 16KB ring */
#define OF_MK   196608   /* 2 x 1KB keep-bit buffers */
#define OF_RED  198656   /* 128 rows x 2 floats: max exchange / lsum combine */
#define OF_BAR  199680   /* mbarriers: KF0-2, KE0-2, MF0-1, ME0-1 (10 x 8B) */
#define SMEM_TOTAL 199808

#define BKF(i) (smb + OF_BAR + (u32)(i)*8u)
#define BKE(i) (smb + OF_BAR + 24u + (u32)(i)*8u)
#define BMF(i) (smb + OF_BAR + 48u + (u32)(i)*8u)
#define BME(i) (smb + OF_BAR + 64u + (u32)(i)*8u)

__device__ __forceinline__ void mwait(u32 addr, u32 ph){
    u32 done;
    asm volatile("{\n\t.reg .pred p;\n\t"
        "mbarrier.try_wait.parity.acquire.cta.shared::cta.b64 p, [%1], %2;\n\t"
        "selp.b32 %0, 1, 0, p;\n\t}"
        : "=r"(done) : "r"(addr), "r"(ph) : "memory");
    if (!done){
        asm volatile("{\n\t.reg .pred P1;\n\t"
            "WL_%=:\n\t"
            "mbarrier.try_wait.parity.acquire.cta.shared::cta.b64 P1, [%0], %1, 0x989680;\n\t"
            "@P1 bra.uni WD_%=;\n\t"
            "bra.uni WL_%=;\n\t"
            "WD_%=:\n\t}"
            :: "r"(addr), "r"(ph) : "memory");
    }
}
__device__ __forceinline__ void marr(u32 addr){
    asm volatile("mbarrier.arrive.shared.b64 _, [%0];" :: "r"(addr) : "memory");
}
__device__ __forceinline__ void mcparr(u32 addr){
    asm volatile("cp.async.mbarrier.arrive.noinc.shared::cta.b64 [%0];" :: "r"(addr) : "memory");
}
__device__ __forceinline__ void bar_pair(int id){
    asm volatile("bar.sync %0, 64;" :: "r"(id) : "memory");
}

__device__ __forceinline__ u32 swa(u32 base, int row, int colb){
    return base + (u32)(row * 256) + (u32)((((colb >> 4) ^ (row & 7)) << 4) + (colb & 15));
}
__device__ __forceinline__ u32 swp(u32 base, int row, int colb){
    return base + (u32)(row * 128) + (u32)(((((colb >> 4) ^ (row & 7)) & 7) << 4) + (colb & 15));
}
__device__ __forceinline__ void ldsm4(u32* r, u32 a){
    asm volatile("ldmatrix.sync.aligned.m8n8.x4.shared.b16 {%0,%1,%2,%3},[%4];"
        : "=r"(r[0]),"=r"(r[1]),"=r"(r[2]),"=r"(r[3]) : "r"(a));
}
__device__ __forceinline__ void ldsm4t(u32* r, u32 a){
    asm volatile("ldmatrix.sync.aligned.m8n8.x4.trans.shared.b16 {%0,%1,%2,%3},[%4];"
        : "=r"(r[0]),"=r"(r[1]),"=r"(r[2]),"=r"(r[3]) : "r"(a));
}
__device__ __forceinline__ void mmaf16(float* c, const u32* a, u32 b0, u32 b1){
    asm volatile("mma.sync.aligned.m16n8k16.row.col.f32.f16.f16.f32 "
        "{%0,%1,%2,%3},{%4,%5,%6,%7},{%8,%9},{%0,%1,%2,%3};"
        : "+f"(c[0]),"+f"(c[1]),"+f"(c[2]),"+f"(c[3])
        : "r"(a[0]),"r"(a[1]),"r"(a[2]),"r"(a[3]),"r"(b0),"r"(b1));
}
// fp32 pair -> packed fp16 hi pair + fp16 lo (residual) pair
__device__ __forceinline__ void split16(float p0, float p1, u32& h2, u32& l2){
    __half2 h = __floats2half2_rn(p0, p1);
    h2 = *(u32*)&h;
    float r0 = p0 - __low2float(h);
    float r1 = p1 - __high2float(h);
    __half2 l = __floats2half2_rn(r0, r1);
    l2 = *(u32*)&l;
}
__device__ __forceinline__ u32 packh(float a, float b){
    __half2 h = __floats2half2_rn(a, b);
    return *(u32*)&h;
}
__device__ __forceinline__ float ex2f(float x){
    float r; asm("ex2.approx.f32 %0, %1;" : "=f"(r) : "f"(x)); return r;
}

// JAX threefry2x32 partitionable, bit-exact (frozen since R1).
__device__ __forceinline__ u32 tf_keep(u32 ctr)
{
    const u32 K1 = 42u;
    const u32 K2 = 0x1BD11BDAu ^ 42u;
    u32 x0 = 0u;
    u32 x1 = ctr + K1;
#define TF_RND(r) { x0 += x1; x1 = __funnelshift_l(x1, x1, (r)); x1 ^= x0; }
    TF_RND(13) TF_RND(15) TF_RND(26) TF_RND(6)
    x0 += K1; x1 += K2 + 1u;
    TF_RND(17) TF_RND(29) TF_RND(16) TF_RND(24)
    x0 += K2; x1 += 0u + 2u;
    TF_RND(13) TF_RND(15) TF_RND(26) TF_RND(6)
    x0 += 0u; x1 += K1 + 3u;
    TF_RND(17) TF_RND(29) TF_RND(16) TF_RND(24)
    x0 += K1; x1 += K2 + 4u;
    TF_RND(13) TF_RND(15) TF_RND(26) TF_RND(6)
    x0 += K2; x1 += 0u + 5u;
#undef TF_RND
    return (((x0 ^ x1) >> 9) <= 6710886u) ? 1u : 0u;
}

__global__ void __launch_bounds__(256)
split_prepass(const float* __restrict__ x1, const float* __restrict__ x2)
{
    int i = blockIdx.x * 256 + threadIdx.x;
    int half = i >> 19;
    int j = i & 0x7FFFF;
    const float4* src = (const float4*)(half ? x2 : x1);
    float4 v = src[j];
    u32 h0,l0,h1,l1;
    split16(v.x, v.y, h0, l0);
    split16(v.z, v.w, h1, l1);
    uint2* dh = (uint2*)(half ? gKH : gQH);
    uint2* dl = (uint2*)(half ? gKL : gQL);
    dh[j] = make_uint2(h0, h1);
    dl[j] = make_uint2(l0, l1);
}

// cp.async one 64-row fp16 K tile pair (hi+lo); 512 threads, 4 chunks each
__device__ __forceinline__ void cp_k(u32 bufbase, int b, int n0, int tid){
    #pragma unroll
    for (int k = 0; k < 4; k++){
        int idx  = tid + k * NCT;
        int half = idx >> 10;
        int ci   = idx & 1023;
        int row  = ci >> 4;
        int c    = ci & 15;
        u32 da = bufbase + (u32)(half * 16384) + (u32)(row * 256) + (u32)((c ^ (row & 7)) << 4);
        const char* s = (const char*)(half ? gKL : gKH)
                      + ((size_t)(b * NNs + n0 + row) * 256 + c * 16);
        asm volatile("cp.async.cg.shared.global [%0], [%1], 16;" :: "r"(da), "l"(s));
    }
}

// PV step (single pass fp16): O += P16 * V16  (V16 = fp16 K-hi tile, trans)
__device__ __forceinline__ void pv_step(float o[8][4], u32 PHb, u32 KHb,
                                        int g, int s, int rA, int cA){
    #pragma unroll
    for (int kk = 0; kk < 4; kk++){
        u32 pA[4];
        ldsm4(pA, swp(PHb, 16 * g + rA, 32 * kk + cA));
        #pragma unroll
        for (int dgp = 0; dgp < 4; dgp++){
            int colb = 128 * s + 32 * dgp + cA;
            u32 bh[4];
            ldsm4t(bh, swa(KHb, 16 * kk + rA, colb));
            mmaf16(o[2*dgp],   pA, bh[0], bh[1]);
            mmaf16(o[2*dgp+1], pA, bh[2], bh[3]);
        }
    }
}

__global__ void __launch_bounds__(TPB, 1)
attn_hmma(const float* __restrict__ x1, const float* __restrict__ x2, float* __restrict__ out)
{
    extern __shared__ char sm[];
    const u32 smb = (u32)__cvta_generic_to_shared(sm);
    const int tid  = threadIdx.x;
    const int w    = tid >> 5;
    const int lane = tid & 31;
    const int gID  = lane >> 2;
    const int tig  = lane & 3;
    const int b    = blockIdx.y;
    const int mrow0 = blockIdx.x * BM;

    // ---- mbarrier init (before ANY arrive) ----
    if (tid == 0){
        #pragma unroll
        for (int i = 0; i < 3; i++){
            asm volatile("mbarrier.init.shared.b64 [%0], %1;" :: "r"(BKF(i)), "r"(NCT) : "memory");
            asm volatile("mbarrier.init.shared.b64 [%0], %1;" :: "r"(BKE(i)), "r"(NCT) : "memory");
        }
        #pragma unroll
        for (int i = 0; i < 2; i++){
            asm volatile("mbarrier.init.shared.b64 [%0], %1;" :: "r"(BMF(i)), "r"(128) : "memory");
            asm volatile("mbarrier.init.shared.b64 [%0], %1;" :: "r"(BME(i)), "r"(NCT) : "memory");
        }
    }
    __syncthreads();

    if (w >= 16){
        // ================= MASK WARPS: free-running threefry producer ======
        int idx = (w - 16) * 32 + lane;     // 0..127 -> row
        u32 base0 = ((u32)(b * Mm + mrow0 + idx)) * 2048u;
        #pragma unroll 1
        for (int t = 0; t < NT; t++){
            if (t >= 2) mwait(BME(t & 1), (u32)(((t >> 1) - 1) & 1));
            u32 base = base0 + (u32)(t * 64);
            u32 m0 = 0, m1 = 0;
            #pragma unroll 4
            for (int j = 0; j < 32; j++){
                m0 |= tf_keep(base + (u32)j) << j;
                m1 |= tf_keep(base + 32u + (u32)j) << j;
            }
            u32* mk = (u32*)(sm + OF_MK + ((t & 1) ? 1024 : 0));
            mk[idx * 2]     = m0;
            mk[idx * 2 + 1] = m1;
            marr(BMF(t & 1));
        }
        return;
    }

    // ================= COMPUTE WARPS =======================================
    const int g = w >> 1;             // row group 0..7
    const int s = w & 1;              // col half
    const u32 QH = smb + OF_QH, QL = smb + OF_QL;
    float* redf = (float*)(sm + OF_RED);

    // prologue: Q hi+lo + K tile 0; single arrive covers both
    #pragma unroll
    for (int k = 0; k < 8; k++){
        int idx = tid + k * NCT;        // 0..4095
        int half = idx >> 11;
        int ci = idx & 2047;
        int row = ci >> 4, c = ci & 15;
        u32 da = (half ? QL : QH) + (u32)(row * 256) + (u32)((c ^ (row & 7)) << 4);
        const char* src = (const char*)(half ? gQL : gQH)
                        + ((size_t)(b * Mm + mrow0 + row) * 256 + c * 16);
        asm volatile("cp.async.cg.shared.global [%0], [%1], 16;" :: "r"(da), "l"(src));
    }
    cp_k(smb + OF_K0, b, 0, tid);
    mcparr(BKF(0));

    const int rA  = ((lane >> 3) & 1) * 8 + (lane & 7);
    const int cA  = ((lane >> 4) & 1) * 16;
    const int rBq = ((lane >> 4) & 1) * 8 + (lane & 7);
    const int cBq = ((lane >> 3) & 1) * 16;
    const int r0  = 16 * g + gID;

    float o[8][4];
    #pragma unroll
    for (int i = 0; i < 8; i++){ o[i][0]=o[i][1]=o[i][2]=o[i][3]=0.f; }
    float lsum0 = 0.f, lsum1 = 0.f;
    float m0r = -1e30f, m1r = -1e30f;    // running max (exp2-arg domain), per row

    #pragma unroll 1
    for (int t = 0; t < NT; t++){
        const int kb = t % 3;
        const u32 KB = smb + OF_K0 + (u32)(kb * 32768);
        const u32 KHt = KB, KLt = KB + 16384;

        // ---- K(t) ready ----
        mwait(BKF(kb), (u32)((t / 3) & 1));

        // ---- QK: S(16x32) = Qh*Kh + Qh*Kl + Ql*Kh (fp16, ~2^-21 accurate) ----
        float s4[4][4];
        #pragma unroll
        for (int i = 0; i < 4; i++){ s4[i][0]=s4[i][1]=s4[i][2]=s4[i][3]=0.f; }

        #pragma unroll
        for (int k = 0; k < 8; k++){
            int dby = k * 32;
            u32 ah[4], al[4];
            ldsm4(ah, swa(QH, 16 * g + rA, dby + cA));
            ldsm4(al, swa(QL, 16 * g + rA, dby + cA));
            #pragma unroll
            for (int nb = 0; nb < 2; nb++){
                u32 bh[4], bl[4];
                ldsm4(bh, swa(KHt, 32 * s + nb * 16 + rBq, dby + cBq));
                ldsm4(bl, swa(KLt, 32 * s + nb * 16 + rBq, dby + cBq));
                mmaf16(s4[2*nb],   ah, bh[0], bh[1]);
                mmaf16(s4[2*nb],   ah, bl[0], bl[1]);
                mmaf16(s4[2*nb],   al, bh[0], bh[1]);
                mmaf16(s4[2*nb+1], ah, bh[2], bh[3]);
                mmaf16(s4[2*nb+1], ah, bl[2], bl[3]);
                mmaf16(s4[2*nb+1], al, bh[2], bh[3]);
            }
        }

        // ---- local per-row tile max over this warp's 32 cols ----
        {
            float t0 = fmaxf(fmaxf(s4[0][0], s4[0][1]), fmaxf(s4[1][0], s4[1][1]));
            t0 = fmaxf(t0, fmaxf(fmaxf(s4[2][0], s4[2][1]), fmaxf(s4[3][0], s4[3][1])));
            float t1 = fmaxf(fmaxf(s4[0][2], s4[0][3]), fmaxf(s4[1][2], s4[1][3]));
            t1 = fmaxf(t1, fmaxf(fmaxf(s4[2][2], s4[2][3]), fmaxf(s4[3][2], s4[3][3])));
            t0 = fmaxf(t0, __shfl_xor_sync(0xffffffffu, t0, 1));
            t0 = fmaxf(t0, __shfl_xor_sync(0xffffffffu, t0, 2));
            t1 = fmaxf(t1, __shfl_xor_sync(0xffffffffu, t1, 1));
            t1 = fmaxf(t1, __shfl_xor_sync(0xffffffffu, t1, 2));
            if (tig == 0){
                redf[r0 * 2 + s]       = t0 * C2;
                redf[(r0 + 8) * 2 + s] = t1 * C2;
            }
        }

        // ---- PV(t-1): single-pass fp16, in old scale m_{t-1} ----
        if (t > 0){
            const int kbp = (t - 1) % 3;
            const u32 KBp = smb + OF_K0 + (u32)(kbp * 32768);
            const u32 PHp = smb + OF_P0 + (u32)(((t - 1) & 1) * 16384);
            pv_step(o, PHp, KBp, g, s, rA, cA);
            marr(BKE(kbp));                    // K(t-1) consumed by this thread
        }

        // ---- pair max exchange; rescale O/lsum to new scale ----
        bar_pair(1 + g);
        float mn0, mn1;
        {
            float tm0 = fmaxf(redf[r0 * 2],       redf[r0 * 2 + 1]);
            float tm1 = fmaxf(redf[(r0 + 8) * 2], redf[(r0 + 8) * 2 + 1]);
            mn0 = fmaxf(m0r, tm0);
            mn1 = fmaxf(m1r, tm1);
            float a0 = ex2f(m0r - mn0);
            float a1 = ex2f(m1r - mn1);
            m0r = mn0; m1r = mn1;
            lsum0 *= a0; lsum1 *= a1;
            #pragma unroll
            for (int db = 0; db < 8; db++){
                o[db][0] *= a0; o[db][1] *= a0;
                o[db][2] *= a1; o[db][3] *= a1;
            }
        }

        // ---- prefetch K(t+1) ----
        if (t < NT - 1){
            if (t >= 2) mwait(BKE((t + 1) % 3), (u32)(((t + 1) / 3 - 1) & 1));
            cp_k(smb + OF_K0 + (u32)(((t + 1) % 3) * 32768), b, (t + 1) * BN, tid);
            mcparr(BKF((t + 1) % 3));
        }

        // ---- mask tile t ----
        mwait(BMF(t & 1), (u32)((t >> 1) & 1));
        const u32* mk = (const u32*)(sm + OF_MK + ((t & 1) ? 1024 : 0));
        u32 mw0 = mk[r0 * 2 + s];
        u32 mw1 = mk[(r0 + 8) * 2 + s];
        marr(BME(t & 1));

        // ---- softmax (normalized) + dropout -> P[t&1] (fp16, p<=1.25) ----
        const u32 PHc = smb + OF_P0 + (u32)((t & 1) * 16384);
        #pragma unroll
        for (int nb = 0; nb < 4; nb++){
            float* c = s4[nb];
            float p0 = ex2f(fmaf(c[0], C2, -mn0));
            float p1 = ex2f(fmaf(c[1], C2, -mn0));
            float p2 = ex2f(fmaf(c[2], C2, -mn1));
            float p3 = ex2f(fmaf(c[3], C2, -mn1));
            lsum0 += p0 + p1;
            lsum1 += p2 + p3;
            int bit = 8 * nb + 2 * tig;
            float q0 = ((mw0 >> bit) & 1u)       ? p0 * INV_KEEP : 0.f;
            float q1 = ((mw0 >> (bit + 1)) & 1u) ? p1 * INV_KEEP : 0.f;
            float q2 = ((mw1 >> bit) & 1u)       ? p2 * INV_KEEP : 0.f;
            float q3 = ((mw1 >> (bit + 1)) & 1u) ? p3 * INV_KEEP : 0.f;
            int colb = 64 * s + 16 * nb + 4 * tig;
            *(u32*)(sm + (swp(PHc, r0,     colb) - smb)) = packh(q0, q1);
            *(u32*)(sm + (swp(PHc, r0 + 8, colb) - smb)) = packh(q2, q3);
        }
        bar_pair(1 + g);                       // P(t) visible within row pair
    }

    // ---- tail: PV(NT-1) ----
    {
        const int kbp = (NT - 1) % 3;
        const u32 KBp = smb + OF_K0 + (u32)(kbp * 32768);
        const u32 PHp = smb + OF_P0 + (u32)(((NT - 1) & 1) * 16384);
        pv_step(o, PHp, KBp, g, s, rA, cA);
    }

    // ---- epilogue: combine pair lsums (same scale: m synced every tile) ----
    lsum0 += __shfl_xor_sync(0xffffffffu, lsum0, 1);
    lsum0 += __shfl_xor_sync(0xffffffffu, lsum0, 2);
    lsum1 += __shfl_xor_sync(0xffffffffu, lsum1, 1);
    lsum1 += __shfl_xor_sync(0xffffffffu, lsum1, 2);
    if (tig == 0){
        redf[r0 * 2 + s]       = lsum0;
        redf[(r0 + 8) * 2 + s] = lsum1;
    }
    bar_pair(1 + g);
    {
        float inv0 = 1.0f / (redf[r0 * 2] + redf[r0 * 2 + 1]);
        float inv1 = 1.0f / (redf[(r0 + 8) * 2] + redf[(r0 + 8) * 2 + 1]);

        float* g0 = out + ((size_t)b * Mm + mrow0 + r0) * Dd + 64 * s;
        float* g1 = g0 + 8 * Dd;
        #pragma unroll
        for (int db = 0; db < 8; db++){
            int d = db * 8 + 2 * tig;
            *(float2*)(g0 + d) = make_float2(o[db][0] * inv0, o[db][1] * inv0);
            *(float2*)(g1 + d) = make_float2(o[db][2] * inv1, o[db][3] * inv1);
        }
    }
}

extern "C" void kernel_launch(void* const* d_in, const int* in_sizes, int n_in,
                              void* d_out, int out_size)
{
    const float* x1 = (const float*)d_in[0];
    const float* x2 = (const float*)d_in[1];
    float* out = (float*)d_out;

    split_prepass<<<4096, 256>>>(x1, x2);

    cudaFuncSetAttribute(attn_hmma, cudaFuncAttributeMaxDynamicSharedMemorySize, SMEM_TOTAL);
    dim3 grid(Mm / BM, Bb);
    attn_hmma<<<grid, TPB, SMEM_TOTAL>>>(x1, x2, out);
}